// round 12
// baseline (speedup 1.0000x reference)
#include <cuda_runtime.h>
#include <cuda_bf16.h>
#include <cstdint>
#include <cstddef>

#define M_DIM 4096
#define N_DIM 8192
#define K_DIM 2048

#define BM 128
#define BN 256
#define BKB 64     // K-bytes per tile (64 int8)
#define SROW 80    // 64 + 16 pad bytes -> conflict-free ldmatrix phases
#define STAGES 4
#define NTHREADS 512

#define TILES_M (M_DIM / BM)   // 32
#define TILES_N (N_DIM / BN)   // 32
#define GROUP_M 8              // raster group height (M-tiles per group)

#define SMEM_A_BYTES (STAGES * BM * SROW)          // 40960
#define SMEM_B_BYTES (STAGES * BN * SROW)          // 81920
#define SMEM_TOTAL   (SMEM_A_BYTES + SMEM_B_BYTES) // 122880 (dynamic; 1 CTA/SM)

#define NX16 (M_DIM * K_DIM / 16)   // 524288  x-chunks (16 int8 each)
#define NW16 (N_DIM * K_DIM / 16)   // 1048576 w-chunks
#define NX4  (M_DIM * K_DIM / 4)
#define NW4  (N_DIM * K_DIM / 4)

// ---------------- scratch (device globals; no allocation allowed) ----------------
__device__ int8_t g_qx[(size_t)M_DIM * K_DIM];   // 8 MB
__device__ int8_t g_qw[(size_t)N_DIM * K_DIM];   // 16 MB
__device__ unsigned g_amax_x;
__device__ unsigned g_amax_w;
__device__ float g_sx, g_sw, g_sprod;

// ---------------- small kernels ----------------
__global__ void reset_kernel() {
    g_amax_x = 0u;
    g_amax_w = 0u;
}

// One launch covers both tensors: blocks [0, XB) scan x, [XB, gridDim.x) scan w.
// __ldcs: pure streaming reads; evict-first keeps L2 clean for useful data.
__global__ void amax_kernel(const float* __restrict__ x, const float* __restrict__ w,
                            int xblocks) {
    const int is_w = (blockIdx.x >= xblocks);
    const float* p = is_w ? w : x;
    const int n4 = is_w ? NW4 : NX4;
    const int nb = is_w ? (gridDim.x - xblocks) : xblocks;
    const int bid = is_w ? (blockIdx.x - xblocks) : blockIdx.x;

    int stride = nb * blockDim.x;
    float m = 0.f;
    for (int i = bid * blockDim.x + threadIdx.x; i < n4; i += stride) {
        float4 v = __ldcs(reinterpret_cast<const float4*>(p) + i);
        m = fmaxf(m, fmaxf(fmaxf(fabsf(v.x), fabsf(v.y)),
                           fmaxf(fabsf(v.z), fabsf(v.w))));
    }
#pragma unroll
    for (int o = 16; o; o >>= 1) m = fmaxf(m, __shfl_xor_sync(0xffffffffu, m, o));
    __shared__ float sm[8];
    int lane = threadIdx.x & 31, wrp = threadIdx.x >> 5;
    if (!lane) sm[wrp] = m;
    __syncthreads();
    if (!wrp) {
        m = (lane < (int)(blockDim.x >> 5)) ? sm[lane] : 0.f;
#pragma unroll
        for (int o = 4; o; o >>= 1) m = fmaxf(m, __shfl_xor_sync(0xffffffffu, m, o));
        if (!lane) {
            // abs-values are non-negative: uint bit-compare is monotonic
            atomicMax(is_w ? &g_amax_w : &g_amax_x, __float_as_uint(m));
        }
    }
}

__global__ void scales_kernel() {
    float ax = __uint_as_float(g_amax_x);
    float aw = __uint_as_float(g_amax_w);
    g_sx = ax / 128.0f;
    g_sw = aw / 127.0f;
    g_sprod = (ax / 128.0f) * (aw / 127.0f);
}

// 16 floats -> 16 int8 per thread (one 16B store). One launch covers x then w
// (split at NX16, a multiple of the block size -> no intra-warp divergence).
// __ldcs on inputs: the fp32 data is never read again; evict-first protects the
// freshly written g_qx/g_qw lines in L2 for the GEMM that launches next.
// IEEE-correct division (__fdiv_rn) matches jnp.round(x / scale) at
// round-half-even tie points regardless of compiler fast-math settings.
__global__ void quant_kernel(const float* __restrict__ x, const float* __restrict__ w) {
    int gi = blockIdx.x * blockDim.x + threadIdx.x;
    const int is_w = (gi >= NX16);
    int i = is_w ? gi - NX16 : gi;
    if (is_w && i >= NW16) return;
    const float* in = is_w ? w : x;
    float s = is_w ? g_sw : g_sx;
    float qmin = is_w ? -127.f : -128.f;
    int8_t* out = is_w ? g_qw : g_qx;
    const float4* src = reinterpret_cast<const float4*>(in) + (size_t)i * 4;
    uint32_t packed[4];
#pragma unroll
    for (int c = 0; c < 4; ++c) {
        float4 v = __ldcs(src + c);
        int q0 = (int)fminf(fmaxf(rintf(__fdiv_rn(v.x, s)), qmin), 127.f);
        int q1 = (int)fminf(fmaxf(rintf(__fdiv_rn(v.y, s)), qmin), 127.f);
        int q2 = (int)fminf(fmaxf(rintf(__fdiv_rn(v.z, s)), qmin), 127.f);
        int q3 = (int)fminf(fmaxf(rintf(__fdiv_rn(v.w, s)), qmin), 127.f);
        packed[c] = (uint32_t)(q0 & 0xff) | ((uint32_t)(q1 & 0xff) << 8) |
                    ((uint32_t)(q2 & 0xff) << 16) | ((uint32_t)(q3 & 0xff) << 24);
    }
    uint4 o = make_uint4(packed[0], packed[1], packed[2], packed[3]);
    reinterpret_cast<uint4*>(out)[i] = o;
}

// ---------------- GEMM helpers ----------------
__device__ __forceinline__ void cp16(void* sm, const void* gm) {
    uint32_t a = (uint32_t)__cvta_generic_to_shared(sm);
    asm volatile("cp.async.cg.shared.global [%0], [%1], 16;\n" :: "r"(a), "l"(gm));
}
__device__ __forceinline__ void cp_commit() { asm volatile("cp.async.commit_group;\n"); }
template <int N>
__device__ __forceinline__ void cp_wait() {
    asm volatile("cp.async.wait_group %0;\n" :: "n"(N));
}

__device__ __forceinline__ void ldsm4(uint32_t* r, const void* p) {
    uint32_t a = (uint32_t)__cvta_generic_to_shared(p);
    asm volatile("ldmatrix.sync.aligned.m8n8.x4.shared.b16 {%0,%1,%2,%3}, [%4];\n"
                 : "=r"(r[0]), "=r"(r[1]), "=r"(r[2]), "=r"(r[3]) : "r"(a));
}

// int8 tensor-core mma: D(s32) = A(s8,16x32) * B(s8,8x32,col) + C
__device__ __forceinline__ void mma16832(int* c, const uint32_t* a, const uint32_t* b) {
    asm volatile(
        "mma.sync.aligned.m16n8k32.row.col.s32.s8.s8.s32 "
        "{%0,%1,%2,%3}, {%4,%5,%6,%7}, {%8,%9}, {%0,%1,%2,%3};\n"
        : "+r"(c[0]), "+r"(c[1]), "+r"(c[2]), "+r"(c[3])
        : "r"(a[0]), "r"(a[1]), "r"(a[2]), "r"(a[3]), "r"(b[0]), "r"(b[1]));
}

// 512 threads load A (128x64 = 512 x 16B chunks) + B (256x64 = 1024 x 16B chunks)
__device__ __forceinline__ void load_tiles(
    int tid, int m0, int n0, int k0,
    int8_t* sA, int8_t* sB) {
    {   // A: one chunk per thread
        int r = tid >> 2, kc = tid & 3;
        cp16(sA + r * SROW + kc * 16,
             g_qx + (size_t)(m0 + r) * K_DIM + k0 + kc * 16);
    }
#pragma unroll
    for (int p = 0; p < 2; ++p) {  // B: two chunks per thread
        int c = tid + p * NTHREADS;
        int r = c >> 2, kc = c & 3;
        cp16(sB + r * SROW + kc * 16,
             g_qw + (size_t)(n0 + r) * K_DIM + k0 + kc * 16);
    }
    cp_commit();
}

__global__ __launch_bounds__(NTHREADS, 1) void gemm_kernel(
    const float* __restrict__ bias, const float* __restrict__ mul_val,
    float* __restrict__ C) {
    extern __shared__ __align__(16) int8_t smem[];
    int8_t* sAbase = smem;                 // [STAGES][BM][SROW]
    int8_t* sBbase = smem + SMEM_A_BYTES;  // [STAGES][BN][SROW]

    const int tid = threadIdx.x;

    // Grouped rasterization: a wave of ~148 CTAs covers an ~8x19 tile block
    // (12 MB operand footprint) instead of a 4.6x32 stripe (17 MB) -> better
    // L2 residency for the quantized operands. Pure permutation of tiles.
    const int pid = blockIdx.x;                        // 0 .. TILES_M*TILES_N-1
    const int num_in_group = GROUP_M * TILES_N;        // 256
    const int group_id = pid / num_in_group;
    const int first_m = group_id * GROUP_M;
    const int rem = pid - group_id * num_in_group;
    const int pid_m = first_m + (rem % GROUP_M);       // TILES_M % GROUP_M == 0
    const int pid_n = rem / GROUP_M;
    const int m0 = pid_m * BM;
    const int n0 = pid_n * BN;

    const int lane = tid & 31, warp = tid >> 5;
    const int wm = (warp & 1) * 64;   // 2 warps over M (128)
    const int wn = (warp >> 1) * 32;  // 8 warps over N (256)

    int acc[4][4][4];
#pragma unroll
    for (int i = 0; i < 4; ++i)
#pragma unroll
        for (int j = 0; j < 4; ++j)
#pragma unroll
            for (int k = 0; k < 4; ++k) acc[i][j][k] = 0;

    const int NT = K_DIM / BKB;  // 32

    // prologue: fill STAGES-1 = 3 stages
#pragma unroll
    for (int s = 0; s < STAGES - 1; ++s)
        load_tiles(tid, m0, n0, s * BKB,
                   sAbase + s * BM * SROW, sBbase + s * BN * SROW);

    int buf = 0;
#pragma unroll 1   // keep mainloop SASS compact (I$-L0 resident, no af/bf lifetime blowup)
    for (int kt = 0; kt < NT; ++kt) {
        cp_wait<STAGES - 2>();   // <=2 groups in flight: stage kt has landed
        __syncthreads();          // everyone finished computing the stage being overwritten
        if (kt + STAGES - 1 < NT) {
            int nbuf = buf + (STAGES - 1);
            if (nbuf >= STAGES) nbuf -= STAGES;
            load_tiles(tid, m0, n0, (kt + STAGES - 1) * BKB,
                       sAbase + nbuf * BM * SROW, sBbase + nbuf * BN * SROW);
        } else {
            cp_commit();          // keep group count in lockstep for the wait above
        }

        const int8_t* sA = sAbase + buf * BM * SROW;
        const int8_t* sB = sBbase + buf * BN * SROW;
#pragma unroll
        for (int kk = 0; kk < BKB; kk += 32) {  // 32 int8 of K per mma step
            uint32_t af[4][4], bf[2][4];
            // A: lanes 0-15 -> rows 0-15 k+0; lanes 16-31 -> rows 0-15 k+16
#pragma unroll
            for (int mi = 0; mi < 4; ++mi)
                ldsm4(af[mi],
                      sA + (wm + mi * 16 + (lane & 15)) * SROW + kk + ((lane >> 4) << 4));
            // B: 0-7 n0-7/k+0, 8-15 n0-7/k+16, 16-23 n8-15/k+0, 24-31 n8-15/k+16
#pragma unroll
            for (int nt = 0; nt < 2; ++nt)
                ldsm4(bf[nt],
                      sB + (wn + nt * 16 + ((lane & 7) | ((lane & 16) >> 1))) * SROW +
                          kk + ((lane & 8) << 1));
#pragma unroll
            for (int mi = 0; mi < 4; ++mi)
#pragma unroll
                for (int ni = 0; ni < 4; ++ni)
                    mma16832(acc[mi][ni], af[mi], &bf[ni >> 1][(ni & 1) * 2]);
        }
        if (++buf == STAGES) buf = 0;
    }

    // epilogue: out = (mul*sx*sw)*acc + (mul*bias)   (acc is exact s32)
    // bias depends only on ni -> load once per ni (4 LDGs/thread, not 16) and
    // pre-multiply by mul. __stcs: C is write-once/streaming; evict-first keeps
    // the 24 MB of quantized operands resident in L2 for the following waves.
    const float fm = mul_val[0];
    const float f1 = fm * g_sprod;
    float2 fmbb[4];
#pragma unroll
    for (int ni = 0; ni < 4; ++ni) {
        int col = n0 + wn + ni * 8 + (lane & 3) * 2;
        float2 bb = *reinterpret_cast<const float2*>(bias + col);
        fmbb[ni].x = fm * bb.x;
        fmbb[ni].y = fm * bb.y;
    }
#pragma unroll
    for (int mi = 0; mi < 4; ++mi) {
#pragma unroll
        for (int ni = 0; ni < 4; ++ni) {
            int row = m0 + wm + mi * 16 + (lane >> 2);
            int col = n0 + wn + ni * 8 + (lane & 3) * 2;
            float2 v0, v1;
            v0.x = f1 * __int2float_rn(acc[mi][ni][0]) + fmbb[ni].x;
            v0.y = f1 * __int2float_rn(acc[mi][ni][1]) + fmbb[ni].y;
            v1.x = f1 * __int2float_rn(acc[mi][ni][2]) + fmbb[ni].x;
            v1.y = f1 * __int2float_rn(acc[mi][ni][3]) + fmbb[ni].y;
            __stcs(reinterpret_cast<float2*>(C + (size_t)row * N_DIM + col), v0);
            __stcs(reinterpret_cast<float2*>(C + (size_t)(row + 8) * N_DIM + col), v1);
        }
    }
}

// ---------------- launch ----------------
extern "C" void kernel_launch(void* const* d_in, const int* in_sizes, int n_in,
                              void* d_out, int out_size) {
    const float* x    = (const float*)d_in[0];   // [4096, 2048]
    const float* w    = (const float*)d_in[1];   // [8192, 2048]
    const float* bias = (const float*)d_in[2];   // [8192]
    const float* mul  = (const float*)d_in[3];   // [1]
    float* out = (float*)d_out;                  // [4096, 8192]

    // opt-in to >48KB dynamic smem (non-stream API; idempotent, capture-safe)
    cudaFuncSetAttribute(gemm_kernel,
                         cudaFuncAttributeMaxDynamicSharedMemorySize, SMEM_TOTAL);

    reset_kernel<<<1, 1>>>();
    // one launch scans both tensors: blocks split 1:2 (x:w, matching sizes)
    amax_kernel<<<3072, 256>>>(x, w, 1024);
    scales_kernel<<<1, 1>>>();
    // one launch quantizes both tensors: (NX16 + NW16) / 256 blocks
    quant_kernel<<<(NX16 + NW16) / 256, 256>>>(x, w);

    gemm_kernel<<<TILES_M * TILES_N, NTHREADS, SMEM_TOTAL>>>(bias, mul, out);
}

// round 15
// speedup vs baseline: 1.1108x; 1.1108x over previous
#include <cuda_runtime.h>
#include <cstdint>
#include <cstddef>

#define M_DIM 4096
#define N_DIM 8192
#define K_DIM 2048

#define BM 128
#define BN 128
#define BKB 64     // K-bytes per tile (64 int8)
#define SROW 80    // 64 + 16 pad bytes -> conflict-free ldmatrix phases
#define STAGES 3
#define NTHREADS 256

#define TILES_M (M_DIM / BM)   // 32
#define TILES_N (N_DIM / BN)   // 64
#define GROUP_M 8              // raster group height (M-tiles per group)

#define SMEM_A_BYTES (STAGES * BM * SROW)          // 30720
#define SMEM_B_BYTES (STAGES * BN * SROW)          // 30720
#define SMEM_TOTAL   (SMEM_A_BYTES + SMEM_B_BYTES) // 61440/CTA -> 2 CTAs/SM = 120KB

#define NX16 (M_DIM * K_DIM / 16)   // 524288
#define NW16 (N_DIM * K_DIM / 16)   // 1048576
#define NX4  (M_DIM * K_DIM / 4)
#define NW4  (N_DIM * K_DIM / 4)

// ---------------- scratch (device globals; no allocation allowed) ----------------
__device__ int8_t g_qx[(size_t)M_DIM * K_DIM];   // 8 MB
__device__ int8_t g_qw[(size_t)N_DIM * K_DIM];   // 16 MB
__device__ unsigned g_amax_x;
__device__ unsigned g_amax_w;
__device__ float g_sx, g_sw, g_sprod;

// ---------------- small kernels (R12-measured: quant 28.6us @ 47% DRAM) -------
__global__ void reset_kernel() {
    g_amax_x = 0u;
    g_amax_w = 0u;
}

__global__ void amax_kernel(const float* __restrict__ x, const float* __restrict__ w,
                            int xblocks) {
    const int is_w = (blockIdx.x >= xblocks);
    const float* p = is_w ? w : x;
    const int n4 = is_w ? NW4 : NX4;
    const int nb = is_w ? (gridDim.x - xblocks) : xblocks;
    const int bid = is_w ? (blockIdx.x - xblocks) : blockIdx.x;

    int stride = nb * blockDim.x;
    float m = 0.f;
    for (int i = bid * blockDim.x + threadIdx.x; i < n4; i += stride) {
        float4 v = __ldcs(reinterpret_cast<const float4*>(p) + i);
        m = fmaxf(m, fmaxf(fmaxf(fabsf(v.x), fabsf(v.y)),
                           fmaxf(fabsf(v.z), fabsf(v.w))));
    }
#pragma unroll
    for (int o = 16; o; o >>= 1) m = fmaxf(m, __shfl_xor_sync(0xffffffffu, m, o));
    __shared__ float sm[8];
    int lane = threadIdx.x & 31, wrp = threadIdx.x >> 5;
    if (!lane) sm[wrp] = m;
    __syncthreads();
    if (!wrp) {
        m = (lane < (int)(blockDim.x >> 5)) ? sm[lane] : 0.f;
#pragma unroll
        for (int o = 4; o; o >>= 1) m = fmaxf(m, __shfl_xor_sync(0xffffffffu, m, o));
        if (!lane) atomicMax(is_w ? &g_amax_w : &g_amax_x, __float_as_uint(m));
    }
}

__global__ void scales_kernel() {
    float ax = __uint_as_float(g_amax_x);
    float aw = __uint_as_float(g_amax_w);
    g_sx = ax / 128.0f;
    g_sw = aw / 127.0f;
    g_sprod = (ax / 128.0f) * (aw / 127.0f);
}

__global__ void quant_kernel(const float* __restrict__ x, const float* __restrict__ w) {
    int gi = blockIdx.x * blockDim.x + threadIdx.x;
    const int is_w = (gi >= NX16);
    int i = is_w ? gi - NX16 : gi;
    if (is_w && i >= NW16) return;
    const float* in = is_w ? w : x;
    float s = is_w ? g_sw : g_sx;
    float qmin = is_w ? -127.f : -128.f;
    int8_t* out = is_w ? g_qw : g_qx;
    const float4* src = reinterpret_cast<const float4*>(in) + (size_t)i * 4;
    uint32_t packed[4];
#pragma unroll
    for (int c = 0; c < 4; ++c) {
        float4 v = __ldcs(src + c);
        int q0 = (int)fminf(fmaxf(rintf(__fdiv_rn(v.x, s)), qmin), 127.f);
        int q1 = (int)fminf(fmaxf(rintf(__fdiv_rn(v.y, s)), qmin), 127.f);
        int q2 = (int)fminf(fmaxf(rintf(__fdiv_rn(v.z, s)), qmin), 127.f);
        int q3 = (int)fminf(fmaxf(rintf(__fdiv_rn(v.w, s)), qmin), 127.f);
        packed[c] = (uint32_t)(q0 & 0xff) | ((uint32_t)(q1 & 0xff) << 8) |
                    ((uint32_t)(q2 & 0xff) << 16) | ((uint32_t)(q3 & 0xff) << 24);
    }
    uint4 o = make_uint4(packed[0], packed[1], packed[2], packed[3]);
    reinterpret_cast<uint4*>(out)[i] = o;
}

// ---------------- GEMM helpers ----------------
__device__ __forceinline__ void cp16(void* sm, const void* gm) {
    uint32_t a = (uint32_t)__cvta_generic_to_shared(sm);
    asm volatile("cp.async.cg.shared.global [%0], [%1], 16;\n" :: "r"(a), "l"(gm));
}
__device__ __forceinline__ void cp_commit() { asm volatile("cp.async.commit_group;\n"); }
template <int N>
__device__ __forceinline__ void cp_wait() {
    asm volatile("cp.async.wait_group %0;\n" :: "n"(N));
}

__device__ __forceinline__ void ldsm4(uint32_t* r, const void* p) {
    uint32_t a = (uint32_t)__cvta_generic_to_shared(p);
    asm volatile("ldmatrix.sync.aligned.m8n8.x4.shared.b16 {%0,%1,%2,%3}, [%4];\n"
                 : "=r"(r[0]), "=r"(r[1]), "=r"(r[2]), "=r"(r[3]) : "r"(a));
}

// int8 tensor-core mma: D(s32) = A(s8,16x32) * B(s8,8x32,col) + C
__device__ __forceinline__ void mma16832(int* c, const uint32_t* a, const uint32_t* b) {
    asm volatile(
        "mma.sync.aligned.m16n8k32.row.col.s32.s8.s8.s32 "
        "{%0,%1,%2,%3}, {%4,%5,%6,%7}, {%8,%9}, {%0,%1,%2,%3};\n"
        : "+r"(c[0]), "+r"(c[1]), "+r"(c[2]), "+r"(c[3])
        : "r"(a[0]), "r"(a[1]), "r"(a[2]), "r"(a[3]), "r"(b[0]), "r"(b[1]));
}

// 256 threads load A (128x64 = 512 x 16B chunks) + B (same): 2 chunks each
__device__ __forceinline__ void load_tiles(
    int tid, int m0, int n0, int k0,
    int8_t* sA, int8_t* sB) {
#pragma unroll
    for (int p = 0; p < 2; ++p) {
        int c = tid + p * NTHREADS;
        int r = c >> 2, kc = c & 3;
        cp16(sA + r * SROW + kc * 16,
             g_qx + (size_t)(m0 + r) * K_DIM + k0 + kc * 16);
    }
#pragma unroll
    for (int p = 0; p < 2; ++p) {
        int c = tid + p * NTHREADS;
        int r = c >> 2, kc = c & 3;
        cp16(sB + r * SROW + kc * 16,
             g_qw + (size_t)(n0 + r) * K_DIM + k0 + kc * 16);
    }
    cp_commit();
}

__global__ __launch_bounds__(NTHREADS, 2) void gemm_kernel(
    const float* __restrict__ bias, const float* __restrict__ mul_val,
    float* __restrict__ C) {
    extern __shared__ __align__(16) int8_t smem[];
    int8_t* sAbase = smem;                 // [STAGES][BM][SROW]
    int8_t* sBbase = smem + SMEM_A_BYTES;  // [STAGES][BN][SROW]

    const int tid = threadIdx.x;

    // grouped raster: wave of ~296 CTAs covers ~8x37 tile block -> L2-friendly
    const int pid = blockIdx.x;                        // 0 .. 2047
    const int num_in_group = GROUP_M * TILES_N;        // 512
    const int group_id = pid / num_in_group;
    const int first_m = group_id * GROUP_M;
    const int rem = pid - group_id * num_in_group;
    const int pid_m = first_m + (rem % GROUP_M);       // TILES_M % GROUP_M == 0
    const int pid_n = rem / GROUP_M;
    const int m0 = pid_m * BM;
    const int n0 = pid_n * BN;

    const int lane = tid & 31, warp = tid >> 5;
    const int wm = (warp & 1) * 64;   // 2 warps over M (128)
    const int wn = (warp >> 1) * 32;  // 4 warps over N (128)

    int acc[4][4][4];
#pragma unroll
    for (int i = 0; i < 4; ++i)
#pragma unroll
        for (int j = 0; j < 4; ++j)
#pragma unroll
            for (int k = 0; k < 4; ++k) acc[i][j][k] = 0;

    const int NT = K_DIM / BKB;  // 32

    // prologue: fill STAGES-1 = 2 stages
#pragma unroll
    for (int s = 0; s < STAGES - 1; ++s)
        load_tiles(tid, m0, n0, s * BKB,
                   sAbase + s * BM * SROW, sBbase + s * BN * SROW);

    int buf = 0;
#pragma unroll 1   // compact mainloop SASS (I$-L0 resident)
    for (int kt = 0; kt < NT; ++kt) {
        cp_wait<STAGES - 2>();   // stage kt landed; later stages may be in flight
        __syncthreads();          // everyone finished computing the stage being overwritten
        if (kt + STAGES - 1 < NT) {
            int nbuf = buf + (STAGES - 1);
            if (nbuf >= STAGES) nbuf -= STAGES;
            load_tiles(tid, m0, n0, (kt + STAGES - 1) * BKB,
                       sAbase + nbuf * BM * SROW, sBbase + nbuf * BN * SROW);
        } else {
            cp_commit();          // keep group count in lockstep for the wait above
        }

        const int8_t* sA = sAbase + buf * BM * SROW;
        const int8_t* sB = sBbase + buf * BN * SROW;
#pragma unroll
        for (int kk = 0; kk < BKB; kk += 32) {  // 32 int8 of K per mma step
            uint32_t af[4][4], bf[2][4];
            // A: lanes 0-15 -> rows 0-15 k+0; lanes 16-31 -> rows 0-15 k+16
#pragma unroll
            for (int mi = 0; mi < 4; ++mi)
                ldsm4(af[mi],
                      sA + (wm + mi * 16 + (lane & 15)) * SROW + kk + ((lane >> 4) << 4));
            // B: 0-7 n0-7/k+0, 8-15 n0-7/k+16, 16-23 n8-15/k+0, 24-31 n8-15/k+16
#pragma unroll
            for (int nt = 0; nt < 2; ++nt)
                ldsm4(bf[nt],
                      sB + (wn + nt * 16 + ((lane & 7) | ((lane & 16) >> 1))) * SROW +
                          kk + ((lane & 8) << 1));
#pragma unroll
            for (int mi = 0; mi < 4; ++mi)
#pragma unroll
                for (int ni = 0; ni < 4; ++ni)
                    mma16832(acc[mi][ni], af[mi], &bf[ni >> 1][(ni & 1) * 2]);
        }
        if (++buf == STAGES) buf = 0;
    }

    // epilogue: out = (mul*sx*sw)*acc + (mul*bias); bias hoisted per-ni;
    // __stcs keeps the 24MB quantized operand set resident in L2.
    const float fm = mul_val[0];
    const float f1 = fm * g_sprod;
    float2 fmbb[4];
#pragma unroll
    for (int ni = 0; ni < 4; ++ni) {
        int col = n0 + wn + ni * 8 + (lane & 3) * 2;
        float2 bb = *reinterpret_cast<const float2*>(bias + col);
        fmbb[ni].x = fm * bb.x;
        fmbb[ni].y = fm * bb.y;
    }
#pragma unroll
    for (int mi = 0; mi < 4; ++mi) {
#pragma unroll
        for (int ni = 0; ni < 4; ++ni) {
            int row = m0 + wm + mi * 16 + (lane >> 2);
            int col = n0 + wn + ni * 8 + (lane & 3) * 2;
            float2 v0, v1;
            v0.x = f1 * __int2float_rn(acc[mi][ni][0]) + fmbb[ni].x;
            v0.y = f1 * __int2float_rn(acc[mi][ni][1]) + fmbb[ni].y;
            v1.x = f1 * __int2float_rn(acc[mi][ni][2]) + fmbb[ni].x;
            v1.y = f1 * __int2float_rn(acc[mi][ni][3]) + fmbb[ni].y;
            __stcs(reinterpret_cast<float2*>(C + (size_t)row * N_DIM + col), v0);
            __stcs(reinterpret_cast<float2*>(C + (size_t)(row + 8) * N_DIM + col), v1);
        }
    }
}

// ---------------- launch ----------------
extern "C" void kernel_launch(void* const* d_in, const int* in_sizes, int n_in,
                              void* d_out, int out_size) {
    const float* x    = (const float*)d_in[0];   // [4096, 2048]
    const float* w    = (const float*)d_in[1];   // [8192, 2048]
    const float* bias = (const float*)d_in[2];   // [8192]
    const float* mul  = (const float*)d_in[3];   // [1]
    float* out = (float*)d_out;                  // [4096, 8192]

    // opt-in to >48KB dynamic smem (non-stream API; idempotent, capture-safe)
    cudaFuncSetAttribute(gemm_kernel,
                         cudaFuncAttributeMaxDynamicSharedMemorySize, SMEM_TOTAL);

    reset_kernel<<<1, 1>>>();
    amax_kernel<<<3072, 256>>>(x, w, 1024);
    scales_kernel<<<1, 1>>>();
    quant_kernel<<<(NX16 + NW16) / 256, 256>>>(x, w);

    gemm_kernel<<<TILES_M * TILES_N, NTHREADS, SMEM_TOTAL>>>(bias, mul, out);
}